// round 7
// baseline (speedup 1.0000x reference)
#include <cuda_runtime.h>
#include <cstdint>

// y[n,j,h,w] = sum_{k,c} s[w+k][c] * wgt[j,k,c];  out[n,j,(h+1)%56,w] = y
//   s[u][c]: u==0||u==57 -> 0 ; u==1 -> x[...,55] (W-roll wrap) ; else x[...,u-2]
// Per tile (n, h-pair): D[128 m, 32 j] = A[128,384] * B[32,384]^T via mma.sync bf16,
// hi/lo split of BOTH operands, 3 passes: AhBh + AlBh + AhBl (proven: rel ~4.7e-6).
// Warp-specialized: warps 0-3 MMA consumers (32m x 32j); warps 4-7 producers do
// LDG -> bf16 split -> swizzled STS directly into double-buffered T (no staging buf).

#define NT      3584
#define NCTA    148
#define THREADS 256

#define SM_WHI  0u          // W hi bf16: [j][384], 768B rows, seg-swizzled
#define SM_WLO  24576u
#define SM_T0H  49152u      // A bf16: [hs][64 u][128 c], 256B rows, seg-swizzled, 32KB
#define SM_T0L  81920u
#define SM_T1H  114688u
#define SM_T1L  147456u
#define SM_TOTAL 180224

static __device__ __forceinline__ uint32_t s2u(const void* p) {
    uint32_t a;
    asm("{ .reg .u64 t; cvta.to.shared.u64 t, %1; cvt.u32.u64 %0, t; }" : "=r"(a) : "l"(p));
    return a;
}
// packed bf16x2: low half <- lo, high half <- hi
static __device__ __forceinline__ uint32_t bf2(float lo, float hi) {
    uint32_t r;
    asm("cvt.rn.bf16x2.f32 %0, %1, %2;" : "=r"(r) : "f"(hi), "f"(lo));
    return r;
}
static __device__ __forceinline__ void ldsm4(uint32_t* r, uint32_t addr) {
    asm volatile("ldmatrix.sync.aligned.m8n8.x4.shared.b16 {%0,%1,%2,%3}, [%4];"
                 : "=r"(r[0]), "=r"(r[1]), "=r"(r[2]), "=r"(r[3]) : "r"(addr));
}
static __device__ __forceinline__ void mma16816(float* c, const uint32_t* a, const uint32_t* b) {
    asm volatile("mma.sync.aligned.m16n8k16.row.col.f32.bf16.bf16.f32 "
                 "{%0,%1,%2,%3}, {%4,%5,%6,%7}, {%8,%9}, {%0,%1,%2,%3};"
                 : "+f"(c[0]), "+f"(c[1]), "+f"(c[2]), "+f"(c[3])
                 : "r"(a[0]), "r"(a[1]), "r"(a[2]), "r"(a[3]), "r"(b[0]), "r"(b[1]));
}

// Produce one tile: x (global) -> THI/TLO bf16 slabs, roll+pad folded into row u.
// Task = (hs, cpg, wp): lane -> c-pair (16) x w-chunk (2 of 4). Conflict-free STS.
static __device__ __forceinline__ void produce_tile(const float* __restrict__ x,
                                                    char* smem, uint32_t dHI, uint32_t dLO,
                                                    int n, int hp, int warp0, int nwarps,
                                                    int lane) {
    const int cpl = lane >> 1;
    const int wc  = lane & 1;
    for (int task = warp0; task < 56; task += nwarps) {
        const int hs  = task / 28;
        const int r   = task % 28;
        const int cpg = r / 7;
        const int wp  = r % 7;
        const int c   = cpg * 32 + cpl * 2;
        const int w0  = wp * 8 + wc * 4;
        const float* src = x + ((size_t)(n * 128 + c) * 56 + hp * 2 + hs) * 56 + w0;
        const float4 va = *(const float4*)src;
        const float4 vb = *(const float4*)(src + 3136);
        const float fa[4] = {va.x, va.y, va.z, va.w};
        const float fb[4] = {vb.x, vb.y, vb.z, vb.w};
        #pragma unroll
        for (int i = 0; i < 4; i++) {
            const int w = w0 + i;
            const int u = (w == 55) ? 1 : (w + 2);
            uint32_t hi = bf2(fa[i], fb[i]);
            float ea = __uint_as_float(hi << 16);
            float eb = __uint_as_float(hi & 0xffff0000u);
            uint32_t lo = bf2(fa[i] - ea, fb[i] - eb);
            uint32_t seg = ((uint32_t)(c >> 3)) ^ (uint32_t)(u & 7);
            uint32_t off = (uint32_t)hs * 16384 + (uint32_t)u * 256
                           + (seg << 4) + ((uint32_t)(c & 7) << 1);
            *(uint32_t*)(smem + dHI + off) = hi;
            *(uint32_t*)(smem + dLO + off) = lo;
        }
    }
}

__global__ __launch_bounds__(THREADS, 1)
void shiftconv_ws2(const float* __restrict__ x,
                   const float* __restrict__ wsrc,
                   float* __restrict__ out) {
    extern __shared__ char smem[];
    const uint32_t sb = s2u(smem);
    const int tid  = threadIdx.x;
    const int lane = tid & 31;
    const int wid  = tid >> 5;

    // ---- one-time: W hi/lo bf16 (seg-swizzled) ----
    for (int i = tid; i < 6144; i += THREADS) {
        int j = i / 192, kp = i % 192, k = kp * 2;
        float2 ab = *(const float2*)(wsrc + j * 384 + k);
        uint32_t hi = bf2(ab.x, ab.y);
        float ea = __uint_as_float(hi << 16);
        float eb = __uint_as_float(hi & 0xffff0000u);
        uint32_t lo = bf2(ab.x - ea, ab.y - eb);
        uint32_t seg = ((uint32_t)(k >> 3)) ^ (uint32_t)(j & 7);
        uint32_t off = (uint32_t)j * 768 + (seg << 4) + ((k & 7) << 1);
        *(uint32_t*)(smem + SM_WHI + off) = hi;
        *(uint32_t*)(smem + SM_WLO + off) = lo;
    }
    // ---- zero pad rows u in {0, 57..63}, both hs, all 4 T slabs ----
    for (int i = tid; i < 4096; i += THREADS) {
        int slab = i >> 10;                 // 0..3 -> T0H,T0L,T1H,T1L
        int rem  = i & 1023;
        int hs   = rem >> 9;
        int rw   = (rem >> 6) & 7;
        int u    = (rw == 0) ? 0 : (56 + rw);
        int wd   = rem & 63;
        uint32_t base = SM_T0H + (uint32_t)slab * 32768u;
        *(uint32_t*)(smem + base + (uint32_t)hs * 16384 + (uint32_t)u * 256
                     + (uint32_t)wd * 4) = 0u;
    }

    // ---- consumer constants (warps 0-3: 32 m-rows x 32 j each) ----
    const int hsub = wid >> 1;
    const int wb0  = (wid & 1) * 32;
    const int g  = lane >> 2, tg = lane & 3;
    const int al = lane & 15;
    const uint32_t ad = (uint32_t)(lane >> 4);
    const int bj = (lane & 7) + ((lane >> 4) << 3);
    const uint32_t bd   = (uint32_t)((lane >> 3) & 1);
    const uint32_t bj7  = (uint32_t)(bj & 7);
    const uint32_t brow0 = (uint32_t)bj * 768;
    const uint32_t brow1 = (uint32_t)(bj + 16) * 768;
    uint32_t abase[2][3], amask[2][3];
    #pragma unroll
    for (int mt = 0; mt < 2; mt++)
        #pragma unroll
        for (int tp = 0; tp < 3; tp++) {
            int u = wb0 + mt * 16 + al + tp; if (u > 63) u = 63;
            abase[mt][tp] = (uint32_t)hsub * 16384 + (uint32_t)u * 256;
            amask[mt][tp] = (uint32_t)(u & 7);
        }

    const int t0 = blockIdx.x;
    __syncthreads();   // W + pad-zero visible

    // ---- prologue: all 8 warps produce tile t0 into T0 ----
    produce_tile(x, smem, SM_T0H, SM_T0L, t0 / 28, t0 % 28, wid, 8, lane);
    __syncthreads();

    int p = 0;
    for (int tt = t0; tt < NT; tt += NCTA) {
        const int n = tt / 28, hp = tt % 28;

        if (wid < 4) {
            const uint32_t tHI = sb + (p ? SM_T1H : SM_T0H);
            const uint32_t tLO = sb + (p ? SM_T1L : SM_T0L);
            float acc[2][4][4];
            #pragma unroll
            for (int mt = 0; mt < 2; mt++)
                #pragma unroll
                for (int nt = 0; nt < 4; nt++)
                    #pragma unroll
                    for (int i = 0; i < 4; i++) acc[mt][nt][i] = 0.f;

            #pragma unroll
            for (int tp = 0; tp < 3; tp++) {
                #pragma unroll
                for (int cb = 0; cb < 8; cb++) {
                    const uint32_t cs = (uint32_t)(cb * 2);
                    const uint32_t aoff0 = abase[0][tp] + (((cs + ad) ^ amask[0][tp]) << 4);
                    const uint32_t aoff1 = abase[1][tp] + (((cs + ad) ^ amask[1][tp]) << 4);
                    uint32_t a0h[4], a0l[4], a1h[4], a1l[4], bh[8], bl[8];
                    ldsm4(a0h, tHI + aoff0);
                    ldsm4(a0l, tLO + aoff0);
                    ldsm4(a1h, tHI + aoff1);
                    ldsm4(a1l, tLO + aoff1);
                    const uint32_t bsg = (uint32_t)(tp * 16) + cs + bd;
                    const uint32_t bo0 = brow0 + ((bsg ^ bj7) << 4);
                    const uint32_t bo1 = brow1 + ((bsg ^ bj7) << 4);
                    ldsm4(bh,     sb + SM_WHI + bo0);
                    ldsm4(bh + 4, sb + SM_WHI + bo1);
                    ldsm4(bl,     sb + SM_WLO + bo0);
                    ldsm4(bl + 4, sb + SM_WLO + bo1);
                    #pragma unroll
                    for (int nt = 0; nt < 4; nt++) {
                        mma16816(acc[0][nt], a0h, bh + nt * 2);
                        mma16816(acc[0][nt], a0l, bh + nt * 2);
                        mma16816(acc[0][nt], a0h, bl + nt * 2);
                        mma16816(acc[1][nt], a1h, bh + nt * 2);
                        mma16816(acc[1][nt], a1l, bh + nt * 2);
                        mma16816(acc[1][nt], a1h, bl + nt * 2);
                    }
                }
            }

            // ---- store with H-roll folded ----
            const int h  = hp * 2 + hsub;
            const int ho = (h + 1) % 56;
            float* ob = out + (size_t)n * 100352 + ho * 56;
            #pragma unroll
            for (int mt = 0; mt < 2; mt++) {
                const int row0 = wb0 + mt * 16 + g;     // <= 55 always
                const int row1 = row0 + 8;
                #pragma unroll
                for (int nt = 0; nt < 4; nt++) {
                    const int j = nt * 8 + tg * 2;
                    ob[(size_t)j * 3136 + row0]       = acc[mt][nt][0];
                    ob[(size_t)(j + 1) * 3136 + row0] = acc[mt][nt][1];
                    if (row1 < 56) {
                        ob[(size_t)j * 3136 + row1]       = acc[mt][nt][2];
                        ob[(size_t)(j + 1) * 3136 + row1] = acc[mt][nt][3];
                    }
                }
            }
        } else {
            // ---- producers: build tile tt+NCTA into the other T buffer ----
            if (tt + NCTA < NT) {
                const int t2 = tt + NCTA;
                produce_tile(x, smem,
                             p ? SM_T0H : SM_T1H, p ? SM_T0L : SM_T1L,
                             t2 / 28, t2 % 28, wid - 4, 4, lane);
            }
        }
        __syncthreads();
        p ^= 1;
    }
}

extern "C" void kernel_launch(void* const* d_in, const int* in_sizes, int n_in,
                              void* d_out, int out_size) {
    const float* x = (const float*)d_in[0];   // (128,128,56,56)
    const float* w = (const float*)d_in[1];   // (32,3,128)
    float* out = (float*)d_out;               // (128,32,56,56)

    cudaFuncSetAttribute(shiftconv_ws2, cudaFuncAttributeMaxDynamicSharedMemorySize, SM_TOTAL);
    shiftconv_ws2<<<NCTA, THREADS, SM_TOTAL>>>(x, w, out);
}

// round 8
// speedup vs baseline: 1.4823x; 1.4823x over previous
#include <cuda_runtime.h>
#include <cstdint>

// y[n,j,h,w] = sum_{k,c} s[w+k][c] * wgt[j,k,c];  out[n,j,(h+1)%56,w] = y
//   s[u][c]: u==0||u==57 -> 0 ; u==1 -> x[...,55] (W-roll wrap) ; else x[...,u-2]
// Per tile (n, h-pair): D[128 m, 32 j] = A[128,384] * B[32,384]^T via mma.sync bf16,
// hi/lo split of BOTH operands, 3 passes: AhBh + AlBh + AhBl (rel ~4.7e-6).
// 512 threads: warps 0-7 MMA consumers (16m x 32j each), warps 8-15 producers
// (LDG -> bf16 split -> swizzled STS into double-buffered T).

#define NT      3584
#define NCTA    148
#define THREADS 512

#define SM_WHI  0u          // W hi bf16: [j][384], 768B rows, seg-swizzled
#define SM_WLO  24576u
#define SM_T0H  49152u      // A bf16: [hs][64 u][128 c], 256B rows, seg-swizzled, 32KB
#define SM_T0L  81920u
#define SM_T1H  114688u
#define SM_T1L  147456u
#define SM_TOTAL 180224

static __device__ __forceinline__ uint32_t s2u(const void* p) {
    uint32_t a;
    asm("{ .reg .u64 t; cvta.to.shared.u64 t, %1; cvt.u32.u64 %0, t; }" : "=r"(a) : "l"(p));
    return a;
}
// packed bf16x2: low half <- lo, high half <- hi
static __device__ __forceinline__ uint32_t bf2(float lo, float hi) {
    uint32_t r;
    asm("cvt.rn.bf16x2.f32 %0, %1, %2;" : "=r"(r) : "f"(hi), "f"(lo));
    return r;
}
static __device__ __forceinline__ void ldsm4(uint32_t* r, uint32_t addr) {
    asm volatile("ldmatrix.sync.aligned.m8n8.x4.shared.b16 {%0,%1,%2,%3}, [%4];"
                 : "=r"(r[0]), "=r"(r[1]), "=r"(r[2]), "=r"(r[3]) : "r"(addr));
}
static __device__ __forceinline__ void mma16816(float* c, const uint32_t* a, const uint32_t* b) {
    asm volatile("mma.sync.aligned.m16n8k16.row.col.f32.bf16.bf16.f32 "
                 "{%0,%1,%2,%3}, {%4,%5,%6,%7}, {%8,%9}, {%0,%1,%2,%3};"
                 : "+f"(c[0]), "+f"(c[1]), "+f"(c[2]), "+f"(c[3])
                 : "r"(a[0]), "r"(a[1]), "r"(a[2]), "r"(a[3]), "r"(b[0]), "r"(b[1]));
}

// Produce one tile: x (global) -> THI/TLO bf16 slabs, roll+pad folded into row u.
static __device__ __forceinline__ void produce_tile(const float* __restrict__ x,
                                                    char* smem, uint32_t dHI, uint32_t dLO,
                                                    int n, int hp, int warp0, int nwarps,
                                                    int lane) {
    const int cpl = lane >> 1;
    const int wc  = lane & 1;
    for (int task = warp0; task < 56; task += nwarps) {
        const int hs  = task / 28;
        const int r   = task % 28;
        const int cpg = r / 7;
        const int wp  = r % 7;
        const int c   = cpg * 32 + cpl * 2;
        const int w0  = wp * 8 + wc * 4;
        const float* src = x + ((size_t)(n * 128 + c) * 56 + hp * 2 + hs) * 56 + w0;
        const float4 va = *(const float4*)src;
        const float4 vb = *(const float4*)(src + 3136);
        const float fa[4] = {va.x, va.y, va.z, va.w};
        const float fb[4] = {vb.x, vb.y, vb.z, vb.w};
        #pragma unroll
        for (int i = 0; i < 4; i++) {
            const int w = w0 + i;
            const int u = (w == 55) ? 1 : (w + 2);
            uint32_t hi = bf2(fa[i], fb[i]);
            float ea = __uint_as_float(hi << 16);
            float eb = __uint_as_float(hi & 0xffff0000u);
            uint32_t lo = bf2(fa[i] - ea, fb[i] - eb);
            uint32_t seg = ((uint32_t)(c >> 3)) ^ (uint32_t)(u & 7);
            uint32_t off = (uint32_t)hs * 16384 + (uint32_t)u * 256
                           + (seg << 4) + ((uint32_t)(c & 7) << 1);
            *(uint32_t*)(smem + dHI + off) = hi;
            *(uint32_t*)(smem + dLO + off) = lo;
        }
    }
}

__global__ __launch_bounds__(THREADS, 1)
void shiftconv_ws3(const float* __restrict__ x,
                   const float* __restrict__ wsrc,
                   float* __restrict__ out) {
    extern __shared__ char smem[];
    const uint32_t sb = s2u(smem);
    const int tid  = threadIdx.x;
    const int lane = tid & 31;
    const int wid  = tid >> 5;

    // ---- one-time: W hi/lo bf16 (seg-swizzled) ----
    for (int i = tid; i < 6144; i += THREADS) {
        int j = i / 192, kp = i % 192, k = kp * 2;
        float2 ab = *(const float2*)(wsrc + j * 384 + k);
        uint32_t hi = bf2(ab.x, ab.y);
        float ea = __uint_as_float(hi << 16);
        float eb = __uint_as_float(hi & 0xffff0000u);
        uint32_t lo = bf2(ab.x - ea, ab.y - eb);
        uint32_t seg = ((uint32_t)(k >> 3)) ^ (uint32_t)(j & 7);
        uint32_t off = (uint32_t)j * 768 + (seg << 4) + ((k & 7) << 1);
        *(uint32_t*)(smem + SM_WHI + off) = hi;
        *(uint32_t*)(smem + SM_WLO + off) = lo;
    }
    // ---- zero pad rows u in {0, 57..63}, both hs, all 4 T slabs ----
    for (int i = tid; i < 4096; i += THREADS) {
        int slab = i >> 10;
        int rem  = i & 1023;
        int hs   = rem >> 9;
        int rw   = (rem >> 6) & 7;
        int u    = (rw == 0) ? 0 : (56 + rw);
        int wd   = rem & 63;
        uint32_t base = SM_T0H + (uint32_t)slab * 32768u;
        *(uint32_t*)(smem + base + (uint32_t)hs * 16384 + (uint32_t)u * 256
                     + (uint32_t)wd * 4) = 0u;
    }

    // ---- consumer constants (warps 0-7: 16 m-rows x 32 j each) ----
    const int hsub = wid >> 2;            // (m = wid*16 + al) >> 6
    const int wm0  = (wid & 3) * 16;      // wpos base within hsub
    const int g  = lane >> 2, tg = lane & 3;
    const int al = lane & 15;
    const uint32_t ad = (uint32_t)(lane >> 4);
    const int bj = (lane & 7) + ((lane >> 4) << 3);
    const uint32_t bd   = (uint32_t)((lane >> 3) & 1);
    const uint32_t bj7  = (uint32_t)(bj & 7);     // == (bj+16)&7
    const uint32_t brow0 = (uint32_t)bj * 768;
    const uint32_t brow1 = (uint32_t)(bj + 16) * 768;
    uint32_t abase[3], amask[3];
    #pragma unroll
    for (int tp = 0; tp < 3; tp++) {
        int u = wm0 + al + tp; if (u > 63) u = 63;
        abase[tp] = (uint32_t)hsub * 16384 + (uint32_t)u * 256;
        amask[tp] = (uint32_t)(u & 7);
    }

    const int t0 = blockIdx.x;
    __syncthreads();   // W + pad-zero visible

    // ---- prologue: all 16 warps produce tile t0 into T0 ----
    produce_tile(x, smem, SM_T0H, SM_T0L, t0 / 28, t0 % 28, wid, 16, lane);
    __syncthreads();

    int p = 0;
    for (int tt = t0; tt < NT; tt += NCTA) {
        const int n = tt / 28, hp = tt % 28;

        if (wid < 8) {
            const uint32_t tHI = sb + (p ? SM_T1H : SM_T0H);
            const uint32_t tLO = sb + (p ? SM_T1L : SM_T0L);
            float acc[4][4];
            #pragma unroll
            for (int nt = 0; nt < 4; nt++)
                #pragma unroll
                for (int i = 0; i < 4; i++) acc[nt][i] = 0.f;

            #pragma unroll
            for (int tp = 0; tp < 3; tp++) {
                #pragma unroll
                for (int cb = 0; cb < 8; cb++) {
                    const uint32_t cs = (uint32_t)(cb * 2);
                    const uint32_t aoff = abase[tp] + (((cs + ad) ^ amask[tp]) << 4);
                    uint32_t ah[4], alr[4], bh[8], bl[8];
                    ldsm4(ah,  tHI + aoff);
                    ldsm4(alr, tLO + aoff);
                    const uint32_t bsg = (uint32_t)(tp * 16) + cs + bd;
                    const uint32_t bo0 = brow0 + ((bsg ^ bj7) << 4);
                    const uint32_t bo1 = brow1 + ((bsg ^ bj7) << 4);
                    ldsm4(bh,     sb + SM_WHI + bo0);
                    ldsm4(bh + 4, sb + SM_WHI + bo1);
                    ldsm4(bl,     sb + SM_WLO + bo0);
                    ldsm4(bl + 4, sb + SM_WLO + bo1);
                    #pragma unroll
                    for (int nt = 0; nt < 4; nt++) {
                        mma16816(acc[nt], ah,  bh + nt * 2);
                        mma16816(acc[nt], alr, bh + nt * 2);
                        mma16816(acc[nt], ah,  bl + nt * 2);
                    }
                }
            }

            // ---- store with H-roll folded ----
            const int h  = hp * 2 + hsub;
            const int ho = (h + 1) % 56;
            float* ob = out + (size_t)n * 100352 + ho * 56;
            const int row0 = wm0 + g;           // <= 55 always
            const int row1 = row0 + 8;
            #pragma unroll
            for (int nt = 0; nt < 4; nt++) {
                const int j = nt * 8 + tg * 2;
                ob[(size_t)j * 3136 + row0]       = acc[nt][0];
                ob[(size_t)(j + 1) * 3136 + row0] = acc[nt][1];
                if (row1 < 56) {
                    ob[(size_t)j * 3136 + row1]       = acc[nt][2];
                    ob[(size_t)(j + 1) * 3136 + row1] = acc[nt][3];
                }
            }
        } else {
            // ---- producers: build tile tt+NCTA into the other T buffer ----
            if (tt + NCTA < NT) {
                const int t2 = tt + NCTA;
                produce_tile(x, smem,
                             p ? SM_T0H : SM_T1H, p ? SM_T0L : SM_T1L,
                             t2 / 28, t2 % 28, wid - 8, 8, lane);
            }
        }
        __syncthreads();
        p ^= 1;
    }
}

extern "C" void kernel_launch(void* const* d_in, const int* in_sizes, int n_in,
                              void* d_out, int out_size) {
    const float* x = (const float*)d_in[0];   // (128,128,56,56)
    const float* w = (const float*)d_in[1];   // (32,3,128)
    float* out = (float*)d_out;               // (128,32,56,56)

    cudaFuncSetAttribute(shiftconv_ws3, cudaFuncAttributeMaxDynamicSharedMemorySize, SM_TOTAL);
    shiftconv_ws3<<<NCTA, THREADS, SM_TOTAL>>>(x, w, out);
}

// round 9
// speedup vs baseline: 1.5518x; 1.0469x over previous
#include <cuda_runtime.h>
#include <cstdint>

// y[n,j,h,w] = sum_{k,c} s[w+k][c] * wgt[j,k,c];  out[n,j,(h+1)%56,w] = y
//   s[u][c]: u==0||u==57 -> 0 ; u==1 -> x[...,55] (W-roll wrap) ; else x[...,u-2]
// Per tile (n, h-pair): D[128 m, 32 j] = A[128,384]*B[32,384]^T via mma.sync bf16,
// hi/lo split of BOTH operands, 3 passes: AhBh + AlBh + AhBl (rel ~4.7e-6).
// 512 threads. Consumers = warps 0-7 in k-split PAIRS: pair i owns a 32m x 32j
// sub-tile, warp (i,kh) covers 12 of 24 k-steps; partials merged via smem.
// Producers = warps 8-15: LDG -> bf16 split -> swizzled STS into double-buffered T.

#define NT      3584
#define NCTA    148
#define THREADS 512

#define SM_WHI  0u          // W hi bf16: [j][384], 768B rows, seg-swizzled
#define SM_WLO  24576u
#define SM_T0H  49152u      // A bf16: [hs][64 u][128 c], 256B rows, seg-swizzled, 32KB
#define SM_T0L  81920u
#define SM_T1H  114688u
#define SM_T1L  147456u
#define SM_RED  180224u     // 4 pairs x 4KB reduction buffers
#define SM_TOTAL 196608

static __device__ __forceinline__ uint32_t s2u(const void* p) {
    uint32_t a;
    asm("{ .reg .u64 t; cvta.to.shared.u64 t, %1; cvt.u32.u64 %0, t; }" : "=r"(a) : "l"(p));
    return a;
}
// packed bf16x2: low half <- lo, high half <- hi
static __device__ __forceinline__ uint32_t bf2(float lo, float hi) {
    uint32_t r;
    asm("cvt.rn.bf16x2.f32 %0, %1, %2;" : "=r"(r) : "f"(hi), "f"(lo));
    return r;
}
static __device__ __forceinline__ void ldsm4(uint32_t* r, uint32_t addr) {
    asm volatile("ldmatrix.sync.aligned.m8n8.x4.shared.b16 {%0,%1,%2,%3}, [%4];"
                 : "=r"(r[0]), "=r"(r[1]), "=r"(r[2]), "=r"(r[3]) : "r"(addr));
}
static __device__ __forceinline__ void mma16816(float* c, const uint32_t* a, const uint32_t* b) {
    asm volatile("mma.sync.aligned.m16n8k16.row.col.f32.bf16.bf16.f32 "
                 "{%0,%1,%2,%3}, {%4,%5,%6,%7}, {%8,%9}, {%0,%1,%2,%3};"
                 : "+f"(c[0]), "+f"(c[1]), "+f"(c[2]), "+f"(c[3])
                 : "r"(a[0]), "r"(a[1]), "r"(a[2]), "r"(a[3]), "r"(b[0]), "r"(b[1]));
}

// Produce one tile: x (global) -> THI/TLO bf16 slabs, roll+pad folded into row u.
static __device__ __forceinline__ void produce_tile(const float* __restrict__ x,
                                                    char* smem, uint32_t dHI, uint32_t dLO,
                                                    int n, int hp, int warp0, int nwarps,
                                                    int lane) {
    const int cpl = lane >> 1;
    const int wc  = lane & 1;
    for (int task = warp0; task < 56; task += nwarps) {
        const int hs  = task / 28;
        const int r   = task % 28;
        const int cpg = r / 7;
        const int wp  = r % 7;
        const int c   = cpg * 32 + cpl * 2;
        const int w0  = wp * 8 + wc * 4;
        const float* src = x + ((size_t)(n * 128 + c) * 56 + hp * 2 + hs) * 56 + w0;
        const float4 va = *(const float4*)src;
        const float4 vb = *(const float4*)(src + 3136);
        const float fa[4] = {va.x, va.y, va.z, va.w};
        const float fb[4] = {vb.x, vb.y, vb.z, vb.w};
        #pragma unroll
        for (int i = 0; i < 4; i++) {
            const int w = w0 + i;
            const int u = (w == 55) ? 1 : (w + 2);
            uint32_t hi = bf2(fa[i], fb[i]);
            float ea = __uint_as_float(hi << 16);
            float eb = __uint_as_float(hi & 0xffff0000u);
            uint32_t lo = bf2(fa[i] - ea, fb[i] - eb);
            uint32_t seg = ((uint32_t)(c >> 3)) ^ (uint32_t)(u & 7);
            uint32_t off = (uint32_t)hs * 16384 + (uint32_t)u * 256
                           + (seg << 4) + ((uint32_t)(c & 7) << 1);
            *(uint32_t*)(smem + dHI + off) = hi;
            *(uint32_t*)(smem + dLO + off) = lo;
        }
    }
}

__global__ __launch_bounds__(THREADS, 1)
void shiftconv_ks(const float* __restrict__ x,
                  const float* __restrict__ wsrc,
                  float* __restrict__ out) {
    extern __shared__ char smem[];
    const uint32_t sb = s2u(smem);
    const int tid  = threadIdx.x;
    const int lane = tid & 31;
    const int wid  = tid >> 5;

    // ---- one-time: W hi/lo bf16 (seg-swizzled) ----
    for (int i = tid; i < 6144; i += THREADS) {
        int j = i / 192, kp = i % 192, k = kp * 2;
        float2 ab = *(const float2*)(wsrc + j * 384 + k);
        uint32_t hi = bf2(ab.x, ab.y);
        float ea = __uint_as_float(hi << 16);
        float eb = __uint_as_float(hi & 0xffff0000u);
        uint32_t lo = bf2(ab.x - ea, ab.y - eb);
        uint32_t seg = ((uint32_t)(k >> 3)) ^ (uint32_t)(j & 7);
        uint32_t off = (uint32_t)j * 768 + (seg << 4) + ((k & 7) << 1);
        *(uint32_t*)(smem + SM_WHI + off) = hi;
        *(uint32_t*)(smem + SM_WLO + off) = lo;
    }
    // ---- zero pad rows u in {0, 57..63}, both hs, all 4 T slabs ----
    for (int i = tid; i < 4096; i += THREADS) {
        int slab = i >> 10;
        int rem  = i & 1023;
        int hs   = rem >> 9;
        int rw   = (rem >> 6) & 7;
        int u    = (rw == 0) ? 0 : (56 + rw);
        int wd   = rem & 63;
        uint32_t base = SM_T0H + (uint32_t)slab * 32768u;
        *(uint32_t*)(smem + base + (uint32_t)hs * 16384 + (uint32_t)u * 256
                     + (uint32_t)wd * 4) = 0u;
    }

    // ---- consumer constants (pairs: 32m x 32j, k-split) ----
    const int pair = wid >> 1;            // 0..3
    const int kh   = wid & 1;             // k-half
    const int hsub = pair >> 1;
    const int wm0  = (pair & 1) * 32;
    const int g  = lane >> 2, tg = lane & 3;
    const int al = lane & 15;
    const uint32_t ad = (uint32_t)(lane >> 4);
    const int bj = (lane & 7) + ((lane >> 4) << 3);
    const uint32_t bd   = (uint32_t)((lane >> 3) & 1);
    const uint32_t bj7  = (uint32_t)(bj & 7);
    const uint32_t brow0 = (uint32_t)bj * 768;
    const uint32_t brow1 = (uint32_t)(bj + 16) * 768;
    uint32_t abase[2][3], amask[2][3];
    #pragma unroll
    for (int mt = 0; mt < 2; mt++)
        #pragma unroll
        for (int tp = 0; tp < 3; tp++) {
            int u = wm0 + mt * 16 + al + tp; if (u > 63) u = 63;
            abase[mt][tp] = (uint32_t)hsub * 16384 + (uint32_t)u * 256;
            amask[mt][tp] = (uint32_t)(u & 7);
        }

    const int t0 = blockIdx.x;
    __syncthreads();   // W + pad-zero visible

    // ---- prologue: all 16 warps produce tile t0 into T0 ----
    produce_tile(x, smem, SM_T0H, SM_T0L, t0 / 28, t0 % 28, wid, 16, lane);
    __syncthreads();

    int p = 0;
    for (int tt = t0; tt < NT; tt += NCTA) {
        const int n = tt / 28, hp = tt % 28;

        if (wid < 8) {
            const uint32_t tHI = sb + (p ? SM_T1H : SM_T0H);
            const uint32_t tLO = sb + (p ? SM_T1L : SM_T0L);
            float acc[2][4][4];
            #pragma unroll
            for (int mt = 0; mt < 2; mt++)
                #pragma unroll
                for (int nt = 0; nt < 4; nt++)
                    #pragma unroll
                    for (int i = 0; i < 4; i++) acc[mt][nt][i] = 0.f;

            // one k-step (compile-time TP, CB)
            #define KSTEP(TP, CB) do {                                               \
                const uint32_t cs = (uint32_t)((CB) * 2);                            \
                const uint32_t aoff0 = abase[0][TP] + (((cs + ad) ^ amask[0][TP]) << 4); \
                const uint32_t aoff1 = abase[1][TP] + (((cs + ad) ^ amask[1][TP]) << 4); \
                uint32_t a0h[4], a0l[4], a1h[4], a1l[4], bh[8], bl[8];               \
                ldsm4(a0h, tHI + aoff0);                                             \
                ldsm4(a0l, tLO + aoff0);                                             \
                ldsm4(a1h, tHI + aoff1);                                             \
                ldsm4(a1l, tLO + aoff1);                                             \
                const uint32_t bsg = (uint32_t)((TP) * 16) + cs + bd;                \
                const uint32_t bo0 = brow0 + ((bsg ^ bj7) << 4);                     \
                const uint32_t bo1 = brow1 + ((bsg ^ bj7) << 4);                     \
                ldsm4(bh,     sb + SM_WHI + bo0);                                    \
                ldsm4(bh + 4, sb + SM_WHI + bo1);                                    \
                ldsm4(bl,     sb + SM_WLO + bo0);                                    \
                ldsm4(bl + 4, sb + SM_WLO + bo1);                                    \
                _Pragma("unroll")                                                    \
                for (int nt = 0; nt < 4; nt++) {                                     \
                    mma16816(acc[0][nt], a0h, bh + nt * 2);                          \
                    mma16816(acc[0][nt], a0l, bh + nt * 2);                          \
                    mma16816(acc[0][nt], a0h, bl + nt * 2);                          \
                    mma16816(acc[1][nt], a1h, bh + nt * 2);                          \
                    mma16816(acc[1][nt], a1l, bh + nt * 2);                          \
                    mma16816(acc[1][nt], a1h, bl + nt * 2);                          \
                }                                                                    \
            } while (0)

            if (kh == 0) {      // k-steps 0..11: tp0 cb0-7, tp1 cb0-3
                KSTEP(0, 0); KSTEP(0, 1); KSTEP(0, 2); KSTEP(0, 3);
                KSTEP(0, 4); KSTEP(0, 5); KSTEP(0, 6); KSTEP(0, 7);
                KSTEP(1, 0); KSTEP(1, 1); KSTEP(1, 2); KSTEP(1, 3);
            } else {            // k-steps 12..23: tp1 cb4-7, tp2 cb0-7
                KSTEP(1, 4); KSTEP(1, 5); KSTEP(1, 6); KSTEP(1, 7);
                KSTEP(2, 0); KSTEP(2, 1); KSTEP(2, 2); KSTEP(2, 3);
                KSTEP(2, 4); KSTEP(2, 5); KSTEP(2, 6); KSTEP(2, 7);
            }
            #undef KSTEP

            // ---- pair reduction via smem (4KB per pair, conflict-free 128b) ----
            char* red = smem + SM_RED + (uint32_t)pair * 4096u;
            if (kh == 1) {
                #pragma unroll
                for (int mt = 0; mt < 2; mt++)
                    #pragma unroll
                    for (int nt = 0; nt < 4; nt++)
                        *((float4*)red + (mt * 4 + nt) * 32 + lane) =
                            make_float4(acc[mt][nt][0], acc[mt][nt][1],
                                        acc[mt][nt][2], acc[mt][nt][3]);
                asm volatile("bar.sync %0, 64;" :: "r"(4 + pair) : "memory");
            } else {
                asm volatile("bar.sync %0, 64;" :: "r"(4 + pair) : "memory");
                #pragma unroll
                for (int mt = 0; mt < 2; mt++)
                    #pragma unroll
                    for (int nt = 0; nt < 4; nt++) {
                        float4 v = *((float4*)red + (mt * 4 + nt) * 32 + lane);
                        acc[mt][nt][0] += v.x; acc[mt][nt][1] += v.y;
                        acc[mt][nt][2] += v.z; acc[mt][nt][3] += v.w;
                    }

                // ---- store with H-roll folded (kh==0 warp only) ----
                const int h  = hp * 2 + hsub;
                const int ho = (h + 1) % 56;
                float* ob = out + (size_t)n * 100352 + ho * 56;
                #pragma unroll
                for (int mt = 0; mt < 2; mt++) {
                    const int row0 = wm0 + mt * 16 + g;   // <= 55 always
                    const int row1 = row0 + 8;
                    #pragma unroll
                    for (int nt = 0; nt < 4; nt++) {
                        const int j = nt * 8 + tg * 2;
                        ob[(size_t)j * 3136 + row0]       = acc[mt][nt][0];
                        ob[(size_t)(j + 1) * 3136 + row0] = acc[mt][nt][1];
                        if (row1 < 56) {
                            ob[(size_t)j * 3136 + row1]       = acc[mt][nt][2];
                            ob[(size_t)(j + 1) * 3136 + row1] = acc[mt][nt][3];
                        }
                    }
                }
            }
        } else {
            // ---- producers: build tile tt+NCTA into the other T buffer ----
            if (tt + NCTA < NT) {
                const int t2 = tt + NCTA;
                produce_tile(x, smem,
                             p ? SM_T0H : SM_T1H, p ? SM_T0L : SM_T1L,
                             t2 / 28, t2 % 28, wid - 8, 8, lane);
            }
        }
        __syncthreads();
        p ^= 1;
    }
}

extern "C" void kernel_launch(void* const* d_in, const int* in_sizes, int n_in,
                              void* d_out, int out_size) {
    const float* x = (const float*)d_in[0];   // (128,128,56,56)
    const float* w = (const float*)d_in[1];   // (32,3,128)
    float* out = (float*)d_out;               // (128,32,56,56)

    cudaFuncSetAttribute(shiftconv_ks, cudaFuncAttributeMaxDynamicSharedMemorySize, SM_TOTAL);
    shiftconv_ks<<<NCTA, THREADS, SM_TOTAL>>>(x, w, out);
}

// round 10
// speedup vs baseline: 1.5695x; 1.0114x over previous
#include <cuda_runtime.h>
#include <cstdint>

// y[n,j,h,w] = sum_{k,c} s[w+k][c] * wgt[j,k,c];  out[n,j,(h+1)%56,w] = y
//   s[u][c]: u==0||u==57 -> 0 ; u==1 -> x[...,55] (W-roll wrap) ; else x[...,u-2]
// Per tile (n, h-pair): D[128 m, 32 j] = A[128,384]*B[32,384]^T via mma.sync bf16,
// hi/lo split of BOTH operands, 3 passes: AhBh + AlBh + AhBl (rel ~4.7e-6).
// 512 threads. Consumers (warps 0-7) in k-split pairs over 32m x 32j sub-tiles;
// producers (warps 8-15) fill double-buffered T. Handoff via mbarriers (no CTA
// convoy): producers run up to 2 tiles ahead; consumers release T right after
// their last ldsm so production overlaps the reduce/store epilogue.

#define NT      3584
#define NCTA    148
#define THREADS 512

#define SM_WHI  0u          // W hi bf16: [j][384], 768B rows, seg-swizzled
#define SM_WLO  24576u
#define SM_T0H  49152u      // A bf16: [hs][64 u][128 c], 256B rows, seg-swizzled, 32KB
#define SM_T0L  81920u
#define SM_T1H  114688u
#define SM_T1L  147456u
#define SM_RED  180224u     // 2 tile-parities x 4 pairs x 4KB reduction buffers
#define SM_BARS 212992u     // full[2], empty[2] mbarriers (8B each)
#define SM_TOTAL 213056

static __device__ __forceinline__ uint32_t s2u(const void* p) {
    uint32_t a;
    asm("{ .reg .u64 t; cvta.to.shared.u64 t, %1; cvt.u32.u64 %0, t; }" : "=r"(a) : "l"(p));
    return a;
}
// packed bf16x2: low half <- lo, high half <- hi
static __device__ __forceinline__ uint32_t bf2(float lo, float hi) {
    uint32_t r;
    asm("cvt.rn.bf16x2.f32 %0, %1, %2;" : "=r"(r) : "f"(hi), "f"(lo));
    return r;
}
static __device__ __forceinline__ void ldsm4(uint32_t* r, uint32_t addr) {
    asm volatile("ldmatrix.sync.aligned.m8n8.x4.shared.b16 {%0,%1,%2,%3}, [%4];"
                 : "=r"(r[0]), "=r"(r[1]), "=r"(r[2]), "=r"(r[3]) : "r"(addr));
}
static __device__ __forceinline__ void mma16816(float* c, const uint32_t* a, const uint32_t* b) {
    asm volatile("mma.sync.aligned.m16n8k16.row.col.f32.bf16.bf16.f32 "
                 "{%0,%1,%2,%3}, {%4,%5,%6,%7}, {%8,%9}, {%0,%1,%2,%3};"
                 : "+f"(c[0]), "+f"(c[1]), "+f"(c[2]), "+f"(c[3])
                 : "r"(a[0]), "r"(a[1]), "r"(a[2]), "r"(a[3]), "r"(b[0]), "r"(b[1]));
}
static __device__ __forceinline__ void mbar_init(uint32_t bar, uint32_t cnt) {
    asm volatile("mbarrier.init.shared.b64 [%0], %1;" :: "r"(bar), "r"(cnt) : "memory");
}
static __device__ __forceinline__ void mbar_arrive(uint32_t bar) {
    asm volatile("mbarrier.arrive.shared.b64 _, [%0];" :: "r"(bar) : "memory");
}
static __device__ __forceinline__ void mbar_wait(uint32_t bar, uint32_t parity) {
    asm volatile(
        "{\n\t.reg .pred P;\n\t"
        "W%=:\n\t"
        "mbarrier.try_wait.parity.shared.b64 P, [%0], %1;\n\t"
        "@P bra.uni D%=;\n\t"
        "bra.uni W%=;\n\t"
        "D%=:\n\t}" :: "r"(bar), "r"(parity) : "memory");
}

// Produce one tile: x (global) -> THI/TLO bf16 slabs, roll+pad folded into row u.
static __device__ __forceinline__ void produce_tile(const float* __restrict__ x,
                                                    char* smem, uint32_t dHI, uint32_t dLO,
                                                    int n, int hp, int warp0, int nwarps,
                                                    int lane) {
    const int cpl = lane >> 1;
    const int wc  = lane & 1;
    #pragma unroll 4
    for (int task = warp0; task < 56; task += nwarps) {
        const int hs  = task / 28;
        const int r   = task % 28;
        const int cpg = r / 7;
        const int wp  = r % 7;
        const int c   = cpg * 32 + cpl * 2;
        const int w0  = wp * 8 + wc * 4;
        const float* src = x + ((size_t)(n * 128 + c) * 56 + hp * 2 + hs) * 56 + w0;
        const float4 va = *(const float4*)src;
        const float4 vb = *(const float4*)(src + 3136);
        const float fa[4] = {va.x, va.y, va.z, va.w};
        const float fb[4] = {vb.x, vb.y, vb.z, vb.w};
        #pragma unroll
        for (int i = 0; i < 4; i++) {
            const int w = w0 + i;
            const int u = (w == 55) ? 1 : (w + 2);
            uint32_t hi = bf2(fa[i], fb[i]);
            float ea = __uint_as_float(hi << 16);
            float eb = __uint_as_float(hi & 0xffff0000u);
            uint32_t lo = bf2(fa[i] - ea, fb[i] - eb);
            uint32_t seg = ((uint32_t)(c >> 3)) ^ (uint32_t)(u & 7);
            uint32_t off = (uint32_t)hs * 16384 + (uint32_t)u * 256
                           + (seg << 4) + ((uint32_t)(c & 7) << 1);
            *(uint32_t*)(smem + dHI + off) = hi;
            *(uint32_t*)(smem + dLO + off) = lo;
        }
    }
}

__global__ __launch_bounds__(THREADS, 1)
void shiftconv_mb(const float* __restrict__ x,
                  const float* __restrict__ wsrc,
                  float* __restrict__ out) {
    extern __shared__ char smem[];
    const uint32_t sb = s2u(smem);
    const int tid  = threadIdx.x;
    const int lane = tid & 31;
    const int wid  = tid >> 5;

    // ---- one-time: W hi/lo bf16 (seg-swizzled) ----
    for (int i = tid; i < 6144; i += THREADS) {
        int j = i / 192, kp = i % 192, k = kp * 2;
        float2 ab = *(const float2*)(wsrc + j * 384 + k);
        uint32_t hi = bf2(ab.x, ab.y);
        float ea = __uint_as_float(hi << 16);
        float eb = __uint_as_float(hi & 0xffff0000u);
        uint32_t lo = bf2(ab.x - ea, ab.y - eb);
        uint32_t seg = ((uint32_t)(k >> 3)) ^ (uint32_t)(j & 7);
        uint32_t off = (uint32_t)j * 768 + (seg << 4) + ((k & 7) << 1);
        *(uint32_t*)(smem + SM_WHI + off) = hi;
        *(uint32_t*)(smem + SM_WLO + off) = lo;
    }
    // ---- zero pad rows u in {0, 57..63}, both hs, all 4 T slabs ----
    for (int i = tid; i < 4096; i += THREADS) {
        int slab = i >> 10;
        int rem  = i & 1023;
        int hs   = rem >> 9;
        int rw   = (rem >> 6) & 7;
        int u    = (rw == 0) ? 0 : (56 + rw);
        int wd   = rem & 63;
        uint32_t base = SM_T0H + (uint32_t)slab * 32768u;
        *(uint32_t*)(smem + base + (uint32_t)hs * 16384 + (uint32_t)u * 256
                     + (uint32_t)wd * 4) = 0u;
    }
    // ---- mbarriers: full[b] (producers arrive), empty[b] (consumers arrive) ----
    const uint32_t barF0 = sb + SM_BARS,      barF1 = sb + SM_BARS + 8;
    const uint32_t barE0 = sb + SM_BARS + 16, barE1 = sb + SM_BARS + 24;
    if (tid == 0) {
        mbar_init(barF0, 256); mbar_init(barF1, 256);
        mbar_init(barE0, 256); mbar_init(barE1, 256);
    }
    __syncthreads();   // W, pad-zero, mbarrier init visible

    const int t0 = blockIdx.x;

    if (wid < 8) {
        // ================= consumers: k-split pairs, 32m x 32j =================
        const int pair = wid >> 1;
        const int kh   = wid & 1;
        const int hsub = pair >> 1;
        const int wm0  = (pair & 1) * 32;
        const int g  = lane >> 2, tg = lane & 3;
        const int al = lane & 15;
        const uint32_t ad = (uint32_t)(lane >> 4);
        const int bj = (lane & 7) + ((lane >> 4) << 3);
        const uint32_t bd   = (uint32_t)((lane >> 3) & 1);
        const uint32_t bj7  = (uint32_t)(bj & 7);
        const uint32_t brow0 = (uint32_t)bj * 768;
        const uint32_t brow1 = (uint32_t)(bj + 16) * 768;
        uint32_t abase[2][3], amask[2][3];
        #pragma unroll
        for (int mt = 0; mt < 2; mt++)
            #pragma unroll
            for (int tp = 0; tp < 3; tp++) {
                int u = wm0 + mt * 16 + al + tp; if (u > 63) u = 63;
                abase[mt][tp] = (uint32_t)hsub * 16384 + (uint32_t)u * 256;
                amask[mt][tp] = (uint32_t)(u & 7);
            }

        int i = 0;
        for (int tt = t0; tt < NT; tt += NCTA, i++) {
            const int n = tt / 28, hp = tt % 28;
            const int b = i & 1;
            mbar_wait(b ? barF1 : barF0, (uint32_t)((i >> 1) & 1));

            const uint32_t tHI = sb + (b ? SM_T1H : SM_T0H);
            const uint32_t tLO = sb + (b ? SM_T1L : SM_T0L);
            float acc[2][4][4];
            #pragma unroll
            for (int mt = 0; mt < 2; mt++)
                #pragma unroll
                for (int nt = 0; nt < 4; nt++)
                    #pragma unroll
                    for (int q = 0; q < 4; q++) acc[mt][nt][q] = 0.f;

            #define KSTEP(TP, CB) do {                                               \
                const uint32_t cs = (uint32_t)((CB) * 2);                            \
                const uint32_t aoff0 = abase[0][TP] + (((cs + ad) ^ amask[0][TP]) << 4); \
                const uint32_t aoff1 = abase[1][TP] + (((cs + ad) ^ amask[1][TP]) << 4); \
                uint32_t a0h[4], a0l[4], a1h[4], a1l[4], bh[8], bl[8];               \
                ldsm4(a0h, tHI + aoff0);                                             \
                ldsm4(a0l, tLO + aoff0);                                             \
                ldsm4(a1h, tHI + aoff1);                                             \
                ldsm4(a1l, tLO + aoff1);                                             \
                const uint32_t bsg = (uint32_t)((TP) * 16) + cs + bd;                \
                const uint32_t bo0 = brow0 + ((bsg ^ bj7) << 4);                     \
                const uint32_t bo1 = brow1 + ((bsg ^ bj7) << 4);                     \
                ldsm4(bh,     sb + SM_WHI + bo0);                                    \
                ldsm4(bh + 4, sb + SM_WHI + bo1);                                    \
                ldsm4(bl,     sb + SM_WLO + bo0);                                    \
                ldsm4(bl + 4, sb + SM_WLO + bo1);                                    \
                _Pragma("unroll")                                                    \
                for (int nt = 0; nt < 4; nt++) {                                     \
                    mma16816(acc[0][nt], a0h, bh + nt * 2);                          \
                    mma16816(acc[0][nt], a0l, bh + nt * 2);                          \
                    mma16816(acc[0][nt], a0h, bl + nt * 2);                          \
                    mma16816(acc[1][nt], a1h, bh + nt * 2);                          \
                    mma16816(acc[1][nt], a1l, bh + nt * 2);                          \
                    mma16816(acc[1][nt], a1h, bl + nt * 2);                          \
                }                                                                    \
            } while (0)

            if (kh == 0) {      // k-steps 0..11
                KSTEP(0, 0); KSTEP(0, 1); KSTEP(0, 2); KSTEP(0, 3);
                KSTEP(0, 4); KSTEP(0, 5); KSTEP(0, 6); KSTEP(0, 7);
                KSTEP(1, 0); KSTEP(1, 1); KSTEP(1, 2); KSTEP(1, 3);
            } else {            // k-steps 12..23
                KSTEP(1, 4); KSTEP(1, 5); KSTEP(1, 6); KSTEP(1, 7);
                KSTEP(2, 0); KSTEP(2, 1); KSTEP(2, 2); KSTEP(2, 3);
                KSTEP(2, 4); KSTEP(2, 5); KSTEP(2, 6); KSTEP(2, 7);
            }
            #undef KSTEP

            // T reads done -> release buffer so producers refill during epilogue
            mbar_arrive(b ? barE1 : barE0);

            // ---- pair reduction (tile-parity double-buffered red) ----
            char* red = smem + SM_RED + (uint32_t)b * 16384u + (uint32_t)pair * 4096u;
            if (kh == 1) {
                #pragma unroll
                for (int mt = 0; mt < 2; mt++)
                    #pragma unroll
                    for (int nt = 0; nt < 4; nt++)
                        *((float4*)red + (mt * 4 + nt) * 32 + lane) =
                            make_float4(acc[mt][nt][0], acc[mt][nt][1],
                                        acc[mt][nt][2], acc[mt][nt][3]);
                asm volatile("bar.sync %0, 64;" :: "r"(4 + pair) : "memory");
            } else {
                asm volatile("bar.sync %0, 64;" :: "r"(4 + pair) : "memory");
                #pragma unroll
                for (int mt = 0; mt < 2; mt++)
                    #pragma unroll
                    for (int nt = 0; nt < 4; nt++) {
                        float4 v = *((float4*)red + (mt * 4 + nt) * 32 + lane);
                        acc[mt][nt][0] += v.x; acc[mt][nt][1] += v.y;
                        acc[mt][nt][2] += v.z; acc[mt][nt][3] += v.w;
                    }
                // ---- store with H-roll folded ----
                const int h  = hp * 2 + hsub;
                const int ho = (h + 1) % 56;
                float* ob = out + (size_t)n * 100352 + ho * 56;
                #pragma unroll
                for (int mt = 0; mt < 2; mt++) {
                    const int row0 = wm0 + mt * 16 + g;   // <= 55 always
                    const int row1 = row0 + 8;
                    #pragma unroll
                    for (int nt = 0; nt < 4; nt++) {
                        const int j = nt * 8 + tg * 2;
                        ob[(size_t)j * 3136 + row0]       = acc[mt][nt][0];
                        ob[(size_t)(j + 1) * 3136 + row0] = acc[mt][nt][1];
                        if (row1 < 56) {
                            ob[(size_t)j * 3136 + row1]       = acc[mt][nt][2];
                            ob[(size_t)(j + 1) * 3136 + row1] = acc[mt][nt][3];
                        }
                    }
                }
            }
        }
    } else {
        // ================= producers: fill T up to 2 tiles ahead =================
        int i = 0;
        for (int tt = t0; tt < NT; tt += NCTA, i++) {
            const int b = i & 1;
            if (i >= 2)
                mbar_wait(b ? barE1 : barE0, (uint32_t)(((i >> 1) - 1) & 1));
            produce_tile(x, smem,
                         b ? SM_T1H : SM_T0H, b ? SM_T1L : SM_T0L,
                         tt / 28, tt % 28, wid - 8, 8, lane);
            mbar_arrive(b ? barF1 : barF0);
        }
    }
}

extern "C" void kernel_launch(void* const* d_in, const int* in_sizes, int n_in,
                              void* d_out, int out_size) {
    const float* x = (const float*)d_in[0];   // (128,128,56,56)
    const float* w = (const float*)d_in[1];   // (32,3,128)
    float* out = (float*)d_out;               // (128,32,56,56)

    cudaFuncSetAttribute(shiftconv_mb, cudaFuncAttributeMaxDynamicSharedMemorySize, SM_TOTAL);
    shiftconv_mb<<<NCTA, THREADS, SM_TOTAL>>>(x, w, out);
}

// round 12
// speedup vs baseline: 1.7162x; 1.0935x over previous
#include <cuda_runtime.h>
#include <cstdint>

// y[n,j,h,w] = sum_{k,c} s[w+k][c] * wgt[j,k,c];  out[n,j,(h+1)%56,w] = y
//   s[u][c]: u==0||u==57 -> 0 ; u==1 -> x[...,55] (W-roll wrap) ; else x[...,u-2]
// Per tile (n, h-pair): D[128 m, 32 j] = A[128,384]*B[32,384]^T via mma.sync bf16,
// hi/lo split of BOTH operands, 3 passes: AhBh + AlBh + AhBl (rel ~4.7e-6).
// 768 threads / 24 warps: warps 0-15 = consumers in 8 k-split pairs, each pair owns
// a 16m x 32j sub-tile (acc 16 regs -> ~65 regs/thread -> 37.5% occupancy);
// warps 16-23 = producers filling double-buffered T via LDG->bf16 split->STS.
// Handoff via mbarriers; consumers release T right after their last ldsm.

#define NT      3584
#define NCTA    148
#define THREADS 768

#define SM_WHI  0u          // W hi bf16: [j][384], 768B rows, seg-swizzled
#define SM_WLO  24576u
#define SM_T0H  49152u      // A bf16: [hs][64 u][128 c], 256B rows, seg-swizzled, 32KB
#define SM_T0L  81920u
#define SM_T1H  114688u
#define SM_T1L  147456u
#define SM_RED  180224u     // 2 parities x 8 pairs x 2KB reduction buffers
#define SM_BARS 212992u     // full[2], empty[2] mbarriers
#define SM_TOTAL 213056

static __device__ __forceinline__ uint32_t s2u(const void* p) {
    uint32_t a;
    asm("{ .reg .u64 t; cvta.to.shared.u64 t, %1; cvt.u32.u64 %0, t; }" : "=r"(a) : "l"(p));
    return a;
}
// packed bf16x2: low half <- lo, high half <- hi
static __device__ __forceinline__ uint32_t bf2(float lo, float hi) {
    uint32_t r;
    asm("cvt.rn.bf16x2.f32 %0, %1, %2;" : "=r"(r) : "f"(hi), "f"(lo));
    return r;
}
static __device__ __forceinline__ void ldsm4(uint32_t* r, uint32_t addr) {
    asm volatile("ldmatrix.sync.aligned.m8n8.x4.shared.b16 {%0,%1,%2,%3}, [%4];"
                 : "=r"(r[0]), "=r"(r[1]), "=r"(r[2]), "=r"(r[3]) : "r"(addr));
}
static __device__ __forceinline__ void mma16816(float* c, const uint32_t* a, const uint32_t* b) {
    asm volatile("mma.sync.aligned.m16n8k16.row.col.f32.bf16.bf16.f32 "
                 "{%0,%1,%2,%3}, {%4,%5,%6,%7}, {%8,%9}, {%0,%1,%2,%3};"
                 : "+f"(c[0]), "+f"(c[1]), "+f"(c[2]), "+f"(c[3])
                 : "r"(a[0]), "r"(a[1]), "r"(a[2]), "r"(a[3]), "r"(b[0]), "r"(b[1]));
}
static __device__ __forceinline__ void mbar_init(uint32_t bar, uint32_t cnt) {
    asm volatile("mbarrier.init.shared.b64 [%0], %1;" :: "r"(bar), "r"(cnt) : "memory");
}
static __device__ __forceinline__ void mbar_arrive(uint32_t bar) {
    asm volatile("mbarrier.arrive.shared.b64 _, [%0];" :: "r"(bar) : "memory");
}
static __device__ __forceinline__ void mbar_wait(uint32_t bar, uint32_t parity) {
    asm volatile(
        "{\n\t.reg .pred P;\n\t"
        "W%=:\n\t"
        "mbarrier.try_wait.parity.shared.b64 P, [%0], %1;\n\t"
        "@P bra.uni D%=;\n\t"
        "bra.uni W%=;\n\t"
        "D%=:\n\t}" :: "r"(bar), "r"(parity) : "memory");
}

// Produce one tile: x (global) -> THI/TLO bf16 slabs, roll+pad folded into row u.
static __device__ __forceinline__ void produce_tile(const float* __restrict__ x,
                                                    char* smem, uint32_t dHI, uint32_t dLO,
                                                    int n, int hp, int warp0, int nwarps,
                                                    int lane) {
    const int cpl = lane >> 1;
    const int wc  = lane & 1;
    #pragma unroll 4
    for (int task = warp0; task < 56; task += nwarps) {
        const int hs  = task / 28;
        const int r   = task % 28;
        const int cpg = r / 7;
        const int wp  = r % 7;
        const int c   = cpg * 32 + cpl * 2;
        const int w0  = wp * 8 + wc * 4;
        const float* src = x + ((size_t)(n * 128 + c) * 56 + hp * 2 + hs) * 56 + w0;
        const float4 va = *(const float4*)src;
        const float4 vb = *(const float4*)(src + 3136);
        const float fa[4] = {va.x, va.y, va.z, va.w};
        const float fb[4] = {vb.x, vb.y, vb.z, vb.w};
        #pragma unroll
        for (int i = 0; i < 4; i++) {
            const int w = w0 + i;
            const int u = (w == 55) ? 1 : (w + 2);
            uint32_t hi = bf2(fa[i], fb[i]);
            float ea = __uint_as_float(hi << 16);
            float eb = __uint_as_float(hi & 0xffff0000u);
            uint32_t lo = bf2(fa[i] - ea, fb[i] - eb);
            uint32_t seg = ((uint32_t)(c >> 3)) ^ (uint32_t)(u & 7);
            uint32_t off = (uint32_t)hs * 16384 + (uint32_t)u * 256
                           + (seg << 4) + ((uint32_t)(c & 7) << 1);
            *(uint32_t*)(smem + dHI + off) = hi;
            *(uint32_t*)(smem + dLO + off) = lo;
        }
    }
}

__global__ __launch_bounds__(THREADS, 1)
void shiftconv_w24(const float* __restrict__ x,
                   const float* __restrict__ wsrc,
                   float* __restrict__ out) {
    extern __shared__ char smem[];
    const uint32_t sb = s2u(smem);
    const int tid  = threadIdx.x;
    const int lane = tid & 31;
    const int wid  = tid >> 5;

    // ---- one-time: W hi/lo bf16 (seg-swizzled) ----
    for (int i = tid; i < 6144; i += THREADS) {
        int j = i / 192, kp = i % 192, k = kp * 2;
        float2 ab = *(const float2*)(wsrc + j * 384 + k);
        uint32_t hi = bf2(ab.x, ab.y);
        float ea = __uint_as_float(hi << 16);
        float eb = __uint_as_float(hi & 0xffff0000u);
        uint32_t lo = bf2(ab.x - ea, ab.y - eb);
        uint32_t seg = ((uint32_t)(k >> 3)) ^ (uint32_t)(j & 7);
        uint32_t off = (uint32_t)j * 768 + (seg << 4) + ((k & 7) << 1);
        *(uint32_t*)(smem + SM_WHI + off) = hi;
        *(uint32_t*)(smem + SM_WLO + off) = lo;
    }
    // ---- zero pad rows u in {0, 57..63}, both hs, all 4 T slabs ----
    for (int i = tid; i < 4096; i += THREADS) {
        int slab = i >> 10;
        int rem  = i & 1023;
        int hs   = rem >> 9;
        int rw   = (rem >> 6) & 7;
        int u    = (rw == 0) ? 0 : (56 + rw);
        int wd   = rem & 63;
        uint32_t base = SM_T0H + (uint32_t)slab * 32768u;
        *(uint32_t*)(smem + base + (uint32_t)hs * 16384 + (uint32_t)u * 256
                     + (uint32_t)wd * 4) = 0u;
    }
    // ---- mbarriers: full[b] <- producers (256 thr), empty[b] <- consumers (512 thr)
    const uint32_t barF0 = sb + SM_BARS,      barF1 = sb + SM_BARS + 8;
    const uint32_t barE0 = sb + SM_BARS + 16, barE1 = sb + SM_BARS + 24;
    if (tid == 0) {
        mbar_init(barF0, 256); mbar_init(barF1, 256);
        mbar_init(barE0, 512); mbar_init(barE1, 512);
    }
    __syncthreads();   // W, pad-zero, mbarrier init visible

    const int t0 = blockIdx.x;

    if (wid < 16) {
        // ======= consumers: 8 k-split pairs, each pair = 16m x 32j sub-tile =======
        const int pr   = wid >> 1;            // 0..7 -> m-subtile (16 rows)
        const int kh   = wid & 1;             // k-half
        const int hsub = pr >> 2;
        const int wm0  = (pr & 3) * 16;
        const int g  = lane >> 2, tg = lane & 3;
        const int al = lane & 15;
        const uint32_t ad = (uint32_t)(lane >> 4);
        const int bj = (lane & 7) + ((lane >> 4) << 3);
        const uint32_t bd   = (uint32_t)((lane >> 3) & 1);
        const uint32_t bj7  = (uint32_t)(bj & 7);
        const uint32_t brow0 = (uint32_t)bj * 768;
        const uint32_t brow1 = (uint32_t)(bj + 16) * 768;
        uint32_t abase[3], amask[3];
        #pragma unroll
        for (int tp = 0; tp < 3; tp++) {
            int u = wm0 + al + tp; if (u > 63) u = 63;
            abase[tp] = (uint32_t)hsub * 16384 + (uint32_t)u * 256;
            amask[tp] = (uint32_t)(u & 7);
        }

        int i = 0;
        for (int tt = t0; tt < NT; tt += NCTA, i++) {
            const int n = tt / 28, hp = tt % 28;
            const int b = i & 1;
            mbar_wait(b ? barF1 : barF0, (uint32_t)((i >> 1) & 1));

            const uint32_t tHI = sb + (b ? SM_T1H : SM_T0H);
            const uint32_t tLO = sb + (b ? SM_T1L : SM_T0L);
            float acc[4][4];
            #pragma unroll
            for (int nt = 0; nt < 4; nt++)
                #pragma unroll
                for (int q = 0; q < 4; q++) acc[nt][q] = 0.f;

            #define KSTEP(TP, CB) do {                                               \
                const uint32_t cs = (uint32_t)((CB) * 2);                            \
                const uint32_t aoff = abase[TP] + (((cs + ad) ^ amask[TP]) << 4);    \
                uint32_t ah[4], alr[4], bh[8], bl[8];                                \
                ldsm4(ah,  tHI + aoff);                                              \
                ldsm4(alr, tLO + aoff);                                              \
                const uint32_t bsg = (uint32_t)((TP) * 16) + cs + bd;                \
                const uint32_t bo0 = brow0 + ((bsg ^ bj7) << 4);                     \
                const uint32_t bo1 = brow1 + ((bsg ^ bj7) << 4);                     \
                ldsm4(bh,     sb + SM_WHI + bo0);                                    \
                ldsm4(bh + 4, sb + SM_WHI + bo1);                                    \
                ldsm4(bl,     sb + SM_WLO + bo0);                                    \
                ldsm4(bl + 4, sb + SM_WLO + bo1);                                    \
                _Pragma("unroll")                                                    \
                for (int nt = 0; nt < 4; nt++) {                                     \
                    mma16816(acc[nt], ah,  bh + nt * 2);                             \
                    mma16816(acc[nt], alr, bh + nt * 2);                             \
                    mma16816(acc[nt], ah,  bl + nt * 2);                             \
                }                                                                    \
            } while (0)

            if (kh == 0) {      // k-steps 0..11
                KSTEP(0, 0); KSTEP(0, 1); KSTEP(0, 2); KSTEP(0, 3);
                KSTEP(0, 4); KSTEP(0, 5); KSTEP(0, 6); KSTEP(0, 7);
                KSTEP(1, 0); KSTEP(1, 1); KSTEP(1, 2); KSTEP(1, 3);
            } else {            // k-steps 12..23
                KSTEP(1, 4); KSTEP(1, 5); KSTEP(1, 6); KSTEP(1, 7);
                KSTEP(2, 0); KSTEP(2, 1); KSTEP(2, 2); KSTEP(2, 3);
                KSTEP(2, 4); KSTEP(2, 5); KSTEP(2, 6); KSTEP(2, 7);
            }
            #undef KSTEP

            // T reads done -> release buffer so producers refill during epilogue
            mbar_arrive(b ? barE1 : barE0);

            // ---- pair reduction (parity-double-buffered, 2KB/pair) ----
            char* red = smem + SM_RED + (uint32_t)b * 16384u + (uint32_t)pr * 2048u;
            if (kh == 1) {
                #pragma unroll
                for (int nt = 0; nt < 4; nt++)
                    *((float4*)red + nt * 32 + lane) =
                        make_float4(acc[nt][0], acc[nt][1], acc[nt][2], acc[nt][3]);
                asm volatile("bar.sync %0, 64;" :: "r"(1 + pr) : "memory");
            } else {
                asm volatile("bar.sync %0, 64;" :: "r"(1 + pr) : "memory");
                #pragma unroll
                for (int nt = 0; nt < 4; nt++) {
                    float4 v = *((float4*)red + nt * 32 + lane);
                    acc[nt][0] += v.x; acc[nt][1] += v.y;
                    acc[nt][2] += v.z; acc[nt][3] += v.w;
                }
                // ---- store with H-roll folded ----
                const int h  = hp * 2 + hsub;
                const int ho = (h + 1) % 56;
                float* ob = out + (size_t)n * 100352 + ho * 56;
                const int row0 = wm0 + g;           // <= 55 always
                const int row1 = row0 + 8;
                #pragma unroll
                for (int nt = 0; nt < 4; nt++) {
                    const int j = nt * 8 + tg * 2;
                    ob[(size_t)j * 3136 + row0]       = acc[nt][0];
                    ob[(size_t)(j + 1) * 3136 + row0] = acc[nt][1];
                    if (row1 < 56) {
                        ob[(size_t)j * 3136 + row1]       = acc[nt][2];
                        ob[(size_t)(j + 1) * 3136 + row1] = acc[nt][3];
                    }
                }
            }
        }
    } else {
        // ================= producers: fill T up to 2 tiles ahead =================
        int i = 0;
        for (int tt = t0; tt < NT; tt += NCTA, i++) {
            const int b = i & 1;
            if (i >= 2)
                mbar_wait(b ? barE1 : barE0, (uint32_t)(((i >> 1) - 1) & 1));
            produce_tile(x, smem,
                         b ? SM_T1H : SM_T0H, b ? SM_T1L : SM_T0L,
                         tt / 28, tt % 28, wid - 16, 8, lane);
            mbar_arrive(b ? barF1 : barF0);
        }
    }
}

extern "C" void kernel_launch(void* const* d_in, const int* in_sizes, int n_in,
                              void* d_out, int out_size) {
    const float* x = (const float*)d_in[0];   // (128,128,56,56)
    const float* w = (const float*)d_in[1];   // (32,3,128)
    float* out = (float*)d_out;               // (128,32,56,56)

    cudaFuncSetAttribute(shiftconv_w24, cudaFuncAttributeMaxDynamicSharedMemorySize, SM_TOTAL);
    shiftconv_w24<<<NCTA, THREADS, SM_TOTAL>>>(x, w, out);
}